// round 12
// baseline (speedup 1.0000x reference)
#include <cuda_runtime.h>
#include <cstdint>

#define SH  68                   // normal smem row stride (floats)
#define SHD 136                  // duplicated-pair row stride (floats)
#define SZ  (64 * SH)
#define NHEADS 8
#define NMAX 2048
#define MASK56 0x00FFFFFFFFFFFFFFull

// smem layout (floats): M | P3(+A-stage) | Mdup | P2dup | Wdup | W2dup
#define OFF_M   0
#define OFF_P3  4352
#define OFF_MD  8704
#define OFF_P2D 17408
#define OFF_WD  26112
#define OFF_W2D 34816
#define SMEM_FLOATS 43520        // 174080 bytes

// ---------------- device scratch ----------------
__device__ float g_powers[NHEADS][16][4096];     // g_powers[h][k] = B_h^k
__device__ float g_sos[4096];
__device__ int   g_key[NMAX];
__device__ int   g_perm[NMAX];

// pure packed FFMA: acc(row-pair) += a2(row-pair) * b2(dup pair) — no MOVs
#define FFMA2P(acc, a2, b2)                                                   \
    asm("fma.rn.f32x2 %0, %1, %2, %0;" : "+l"(acc) : "l"(a2), "l"(b2))

__device__ __forceinline__ float f2lo(unsigned long long v) {
    return __uint_as_float((unsigned)(v & 0xffffffffull));
}
__device__ __forceinline__ float f2hi(unsigned long long v) {
    return __uint_as_float((unsigned)(v >> 32));
}

// ---- 64x64 mm core (512 thr): result = (AT)^T * Bdup.
// Lane tile 2 rows x 4 cols; acc[c] = packed (C[r0][c0+c], C[r0+1][c0+c]).
// Per j: LDS.64 (A row-pair) + 2x LDS.128 (B dup pairs) + 4 FFMA2. No MOVs.
__device__ __forceinline__ void mm_acc4(const float* __restrict__ AT,
                                        const float* __restrict__ BD,
                                        unsigned long long acc[4],
                                        int r0, int c0) {
    const float* ap = AT + r0;
    const float* bp = BD + (c0 << 1);
    acc[0] = acc[1] = acc[2] = acc[3] = 0ull;
#pragma unroll 8
    for (int j = 0; j < 64; j++) {
        unsigned long long a2 = *(const unsigned long long*)(ap + j * SH);
        ulonglong2 q0 = *(const ulonglong2*)(bp + j * SHD);
        ulonglong2 q1 = *(const ulonglong2*)(bp + j * SHD + 4);
        FFMA2P(acc[0], a2, q0.x);
        FFMA2P(acc[1], a2, q0.y);
        FFMA2P(acc[2], a2, q1.x);
        FFMA2P(acc[3], a2, q1.y);
    }
}

// store float4 of values as duplicated pairs at row r, cols c0..c0+3
__device__ __forceinline__ void store_dup(float* __restrict__ D, int r, int c0,
                                          float4 v) {
    float* p = D + r * SHD + (c0 << 1);
    *(float4*)(p)     = make_float4(v.x, v.x, v.y, v.y);
    *(float4*)(p + 4) = make_float4(v.z, v.z, v.w, v.w);
}

// gather 4 logical values from a duplicated row
__device__ __forceinline__ float4 load_dup4(const float* __restrict__ D,
                                            int r, int c0) {
    const float* p = D + r * SHD + (c0 << 1);
    float4 a = *(const float4*)(p);
    float4 b = *(const float4*)(p + 4);
    return make_float4(a.x, a.z, b.x, b.z);
}

// ============ kernel A: prepare + steps + grouping, 146 blocks =============
//   b 0..79  : expm(k*H_h)  (h = b/10, k = b%10 + 1)   [deg-9 PS, 4 matmuls]
//   b 80     : expm(H_sos)
//   b 81..144: steps, 32 rows per block
//   b 145    : grouping
__global__ void __launch_bounds__(512, 1)
kernelA(const float* __restrict__ raw, const int* __restrict__ pw, int L,
        float* __restrict__ steps_out, int has_steps) {
    extern __shared__ float sm[];
    int b = blockIdx.x;
    int tid = threadIdx.x;

    if (b >= 81 && b <= 144) {   // ---------------- steps ----------------
        if (has_steps) {
            unsigned long long* tbl = (unsigned long long*)sm;   // 2048 packs
#pragma unroll
            for (int q = 0; q < 4; q++) {
                int n = (tid << 2) + q;
                const int* p = pw + (size_t)n * L;
                unsigned long long pack = 0ull;
                int len = 0;
                for (int t = 0; t < L; t++) {
                    int wv = p[t];
                    int code = (wv == -1) ? 0 : wv;
                    pack |= ((unsigned long long)(code & 3)) << (2 * t);
                    if (wv != 3) len++;                  // PAD = 3
                }
                tbl[n] = pack | ((unsigned long long)len << 56);
            }
            __syncthreads();
            int i0 = (b - 81) << 5;                      // 32 rows per block
            int j0 = tid << 2;
            unsigned long long pj0 = tbl[j0], pj1 = tbl[j0 + 1];
            unsigned long long pj2 = tbl[j0 + 2], pj3 = tbl[j0 + 3];
#pragma unroll 4
            for (int rr = 0; rr < 32; rr++) {
                int i = i0 + rr;
                unsigned long long pi = tbl[i];
                int li = (int)(pi >> 56);
                unsigned long long pjs[4] = {pj0, pj1, pj2, pj3};
                float v[4];
#pragma unroll
                for (int q = 0; q < 4; q++) {
                    unsigned long long pj = pjs[q];
                    int lj = (int)(pj >> 56);
                    unsigned long long d = (pi ^ pj) & MASK56;
                    int pos = d ? ((__ffsll((long long)d) - 1) >> 1) : 64;
                    int mn = min(li, lj), mx = max(li, lj);
                    v[q] = (float)(mx - min(pos, mn));
                }
                __stcs((float4*)(steps_out + (size_t)i * NMAX + j0),
                       make_float4(v[0], v[1], v[2], v[3]));
            }
        }
        cudaTriggerProgrammaticLaunchCompletion();
        return;
    }

    if (b == 145) {   // ---------------- grouping ----------------
        int* cnt = (int*)sm;
        int* off = cnt + 32;
        if (tid < 20) cnt[tid] = 0;
        __syncthreads();
        for (int n = tid; n < NMAX; n += 512) {
            const int* p = pw + (size_t)n * L;
            int c = 0;
            for (int t = 0; t < L; t++) c += (p[t] == 1);
            int key = (p[0] == -1) ? 100 : c;
            g_key[n] = key;
            atomicAdd(&cnt[(key == 100) ? 16 : key], 1);
        }
        __syncthreads();
        if (tid == 0) { int s = 0; for (int q = 0; q < 20; q++) { off[q] = s; s += cnt[q]; } }
        __syncthreads();
        for (int n = tid; n < NMAX; n += 512) {
            int key = g_key[n];
            int pos = atomicAdd(&off[(key == 100) ? 16 : key], 1);
            g_perm[pos] = n;
        }
        cudaTriggerProgrammaticLaunchCompletion();
        return;
    }

    // ---------------- prepare: B_h^k = expm(k*H_h), deg-9 PS --------------
    int h, kk;
    const float* A;
    if (b == 80) { h = -1; kk = 1; A = raw + (size_t)16 * 4096; }
    else         { h = b / 10; kk = b % 10 + 1; A = raw + (size_t)(8 + h) * 4096; }

    float* M   = sm + OFF_M;
    float* P3  = sm + OFF_P3;    // also A-staging buffer
    float* Md  = sm + OFF_MD;
    float* P2d = sm + OFF_P2D;
    float* Wd  = sm + OFF_WD;
    float* W2d = sm + OFF_W2D;

    // 16 warps: row-group w&7 (8 rows), col-half w>>3 (32 cols)
    int w = tid >> 5, l = tid & 31;
    int r0 = (w & 7) * 8 + (l >> 3) * 2;
    int c0 = (w >> 3) * 32 + (l & 7) * 4;

    // Stage A coalesced into P3 slot
    {
        int rr = tid >> 3;
        int cc0 = (tid & 7) << 3;
        float4 a0 = *(const float4*)(A + rr * 64 + cc0);
        float4 a1 = *(const float4*)(A + rr * 64 + cc0 + 4);
        *(float4*)(P3 + rr * SH + cc0)     = a0;
        *(float4*)(P3 + rr * SH + cc0 + 4) = a1;
    }
    __syncthreads();

    // M = k*(A - A^T)/64, normal + duplicated
    float scale = (float)kk * (1.0f / 64.0f);
    for (int i = tid; i < 4096; i += 512) {
        int rr = i >> 6, cc = i & 63;
        float v = (P3[rr * SH + cc] - P3[cc * SH + rr]) * scale;
        M[rr * SH + cc] = v;
        Md[rr * SHD + (cc << 1)]     = v;
        Md[rr * SHD + (cc << 1) + 1] = v;
    }
    __syncthreads();

    unsigned long long acc[4];

    // P2 = M*M = -(Mt*M)  -> dup only
    mm_acc4(M, Md, acc, r0, c0);
    store_dup(P2d, r0,     c0, make_float4(-f2lo(acc[0]), -f2lo(acc[1]),
                                           -f2lo(acc[2]), -f2lo(acc[3])));
    store_dup(P2d, r0 + 1, c0, make_float4(-f2hi(acc[0]), -f2hi(acc[1]),
                                           -f2hi(acc[2]), -f2hi(acc[3])));
    __syncthreads();

    // P3 = M*P2 = -(Mt*P2) -> normal (A-operand); fused W = B2 (dup)
    mm_acc4(M, P2d, acc, r0, c0);
#pragma unroll
    for (int i = 0; i < 2; i++) {
        int r = r0 + i;
        float4 p3v = i ? make_float4(-f2hi(acc[0]), -f2hi(acc[1]),
                                     -f2hi(acc[2]), -f2hi(acc[3]))
                       : make_float4(-f2lo(acc[0]), -f2lo(acc[1]),
                                     -f2lo(acc[2]), -f2lo(acc[3]));
        *(float4*)(P3 + r * SH + c0) = p3v;          // staged A fully consumed
        float4 mv  = *(const float4*)(M + r * SH + c0);
        float4 p2v = load_dup4(P2d, r, c0);
        float4 dg  = make_float4(r == c0 ? 1.f : 0.f, r == c0 + 1 ? 1.f : 0.f,
                                 r == c0 + 2 ? 1.f : 0.f, r == c0 + 3 ? 1.f : 0.f);
        float4 wv;
        wv.x = 1.38888889e-3f * dg.x + 1.98412698e-4f * mv.x
             + 2.48015873e-5f * p2v.x + 2.75573192e-6f * p3v.x;
        wv.y = 1.38888889e-3f * dg.y + 1.98412698e-4f * mv.y
             + 2.48015873e-5f * p2v.y + 2.75573192e-6f * p3v.y;
        wv.z = 1.38888889e-3f * dg.z + 1.98412698e-4f * mv.z
             + 2.48015873e-5f * p2v.z + 2.75573192e-6f * p3v.z;
        wv.w = 1.38888889e-3f * dg.w + 1.98412698e-4f * mv.w
             + 2.48015873e-5f * p2v.w + 2.75573192e-6f * p3v.w;
        store_dup(Wd, r, c0, wv);
    }
    __syncthreads();

    // T1 = B1 - (P3t*W) -> W2 dup;  B1 = I/6 + M/24 + P2/120
    mm_acc4(P3, Wd, acc, r0, c0);
#pragma unroll
    for (int i = 0; i < 2; i++) {
        int r = r0 + i;
        float4 pv = i ? make_float4(f2hi(acc[0]), f2hi(acc[1]),
                                    f2hi(acc[2]), f2hi(acc[3]))
                      : make_float4(f2lo(acc[0]), f2lo(acc[1]),
                                    f2lo(acc[2]), f2lo(acc[3]));
        float4 mv  = *(const float4*)(M + r * SH + c0);
        float4 p2v = load_dup4(P2d, r, c0);
        float4 dg  = make_float4(r == c0 ? 1.f : 0.f, r == c0 + 1 ? 1.f : 0.f,
                                 r == c0 + 2 ? 1.f : 0.f, r == c0 + 3 ? 1.f : 0.f);
        float4 wv;
        wv.x = (1.f / 6.f) * dg.x + (1.f / 24.f) * mv.x + (1.f / 120.f) * p2v.x - pv.x;
        wv.y = (1.f / 6.f) * dg.y + (1.f / 24.f) * mv.y + (1.f / 120.f) * p2v.y - pv.y;
        wv.z = (1.f / 6.f) * dg.z + (1.f / 24.f) * mv.z + (1.f / 120.f) * p2v.z - pv.z;
        wv.w = (1.f / 6.f) * dg.w + (1.f / 24.f) * mv.w + (1.f / 120.f) * p2v.w - pv.w;
        store_dup(W2d, r, c0, wv);
    }
    __syncthreads();

    // E = B0 - (P3t*W2);  B0 = I + M + P2/2
    mm_acc4(P3, W2d, acc, r0, c0);
    float* dst = (h < 0) ? g_sos : g_powers[h][kk];
#pragma unroll
    for (int i = 0; i < 2; i++) {
        int r = r0 + i;
        float4 pv = i ? make_float4(f2hi(acc[0]), f2hi(acc[1]),
                                    f2hi(acc[2]), f2hi(acc[3]))
                      : make_float4(f2lo(acc[0]), f2lo(acc[1]),
                                    f2lo(acc[2]), f2lo(acc[3]));
        float4 mv  = *(const float4*)(M + r * SH + c0);
        float4 p2v = load_dup4(P2d, r, c0);
        float4 dg  = make_float4(r == c0 ? 1.f : 0.f, r == c0 + 1 ? 1.f : 0.f,
                                 r == c0 + 2 ? 1.f : 0.f, r == c0 + 3 ? 1.f : 0.f);
        float4 ev;
        ev.x = dg.x + mv.x + 0.5f * p2v.x - pv.x;
        ev.y = dg.y + mv.y + 0.5f * p2v.y - pv.y;
        ev.z = dg.z + mv.z + 0.5f * p2v.z - pv.z;
        ev.w = dg.w + mv.w + 0.5f * p2v.w - pv.w;
        *(float4*)(dst + r * 64 + c0) = ev;
        if (h >= 0 && kk == 1)       // publish identity as power 0 once per head
            *(float4*)(g_powers[h][0] + r * 64 + c0) = dg;
    }
    cudaTriggerProgrammaticLaunchCompletion();
}

// =================== kernel B: maps gather-broadcast (256 MB) ==============
__global__ void __launch_bounds__(256)
maps_writer(float4* __restrict__ out) {
    cudaGridDependencySynchronize();       // PDL: wait for kernelA's writes
    int b = blockIdx.x;
    int h = b & 7;
    int base = (b >> 3) << 3;
    int t = threadIdx.x;
    float4 v0, v1, v2, v3;
    int cached = -12345;
#pragma unroll 1
    for (int e = 0; e < 8; e++) {
        int n = g_perm[base + e];
        int key = g_key[n];
        if (key != cached) {
            const float4* src = (key == 100) ? (const float4*)g_sos
                                             : (const float4*)g_powers[h][key];
            v0 = src[t]; v1 = src[t + 256]; v2 = src[t + 512]; v3 = src[t + 768];
            cached = key;
        }
        float4* dst = out + ((size_t)((unsigned)(n * NHEADS + h)) << 10);
        __stcs(dst + t,       v0);
        __stcs(dst + t + 256, v1);
        __stcs(dst + t + 512, v2);
        __stcs(dst + t + 768, v3);
    }
}

// ---------------- launch --------------------------------------------------
extern "C" void kernel_launch(void* const* d_in, const int* in_sizes, int n_in,
                              void* d_out, int out_size) {
    const float* raw = (const float*)d_in[0];
    const int*   pw  = (const int*)d_in[1];
    const int L = in_sizes[1] / NMAX;
    float* out = (float*)d_out;

    size_t maps_elems = (size_t)NMAX * NHEADS * 4096;
    int has_steps = ((size_t)out_size >= maps_elems + (size_t)NMAX * NMAX) ? 1 : 0;

    size_t smem = (size_t)SMEM_FLOATS * sizeof(float);   // 174080 B
    cudaFuncSetAttribute(kernelA, cudaFuncAttributeMaxDynamicSharedMemorySize,
                         (int)smem);

    kernelA<<<146, 512, smem>>>(raw, pw, L, out + maps_elems, has_steps);

    cudaLaunchConfig_t cfg = {};
    cfg.gridDim = dim3(2048);
    cfg.blockDim = dim3(256);
    cfg.dynamicSmemBytes = 0;
    cfg.stream = 0;
    cudaLaunchAttribute attrs[1];
    attrs[0].id = cudaLaunchAttributeProgrammaticStreamSerialization;
    attrs[0].val.programmaticStreamSerializationAllowed = 1;
    cfg.attrs = attrs;
    cfg.numAttrs = 1;
    cudaLaunchKernelEx(&cfg, maps_writer, (float4*)out);
}